// round 8
// baseline (speedup 1.0000x reference)
#include <cuda_runtime.h>
#include <stdint.h>

// kNN: B=2, N=2048, D=16, K=16. Output (B,N,K,2) FLOAT32: [b, idx].
//
// transpose_kernel: AoS points -> SoA float4 scratch (coalesced loads).
// knn_kernel: warp-per-query (8 warps/CTA). Per-lane BRANCH-FREE sorted top-4
// (select network, stable strict-<, ties -> lower index = jax.lax.top_k),
// 2-step interleaved distance pass, 16-round warp-min merge over 64-bit keys
// (dist_bits<<32 | idx). Guard: lane that pops all 4 may have discarded a
// needed 5th -> warp re-runs with depth-16 SMEM path (~3% of warps).

#define NPTS 2048
#define KNN  16
#define KL   4
#define WPC  8
#define THREADS (WPC * 32)

__device__ float4 T4g[2][4][NPTS];   // 256 KB static scratch

__global__ void transpose_kernel(const float* __restrict__ points)
{
    int idx = blockIdx.x * blockDim.x + threadIdx.x;   // b*8192 + c*2048 + j
    if (idx >= 2 * 4 * NPTS) return;
    int j = idx & (NPTS - 1);
    int c = (idx >> 11) & 3;
    int b = idx >> 13;
    const float4* P4 = reinterpret_cast<const float4*>(points);
    T4g[b][c][j] = P4[(b * NPTS + j) * 4 + c];
}

__device__ __forceinline__ unsigned dist_key(
    float4 q0, float4 q1, float4 q2, float4 q3,
    float4 a0, float4 a1, float4 a2, float4 a3)
{
    float s = 0.0f, d;
    d = q0.x - a0.x; s = fmaf(d, d, s);
    d = q0.y - a0.y; s = fmaf(d, d, s);
    d = q0.z - a0.z; s = fmaf(d, d, s);
    d = q0.w - a0.w; s = fmaf(d, d, s);
    d = q1.x - a1.x; s = fmaf(d, d, s);
    d = q1.y - a1.y; s = fmaf(d, d, s);
    d = q1.z - a1.z; s = fmaf(d, d, s);
    d = q1.w - a1.w; s = fmaf(d, d, s);
    d = q2.x - a2.x; s = fmaf(d, d, s);
    d = q2.y - a2.y; s = fmaf(d, d, s);
    d = q2.z - a2.z; s = fmaf(d, d, s);
    d = q2.w - a2.w; s = fmaf(d, d, s);
    d = q3.x - a3.x; s = fmaf(d, d, s);
    d = q3.y - a3.y; s = fmaf(d, d, s);
    d = q3.z - a3.z; s = fmaf(d, d, s);
    d = q3.w - a3.w; s = fmaf(d, d, s);
    return __float_as_uint(__fsqrt_rn(s));   // compare post-sqrt (ref semantics)
}

// Branch-free stable insert of (kb,jb) into sorted-ascending 4-list.
// Strict < everywhere: new (later-scanned) key goes after equal keys.
#define INSERT4(kb, jb) do {                                                   \
    const unsigned _k = (kb); const int _j = (jb);                             \
    bool p0 = _k < D[0], p1 = _k < D[1], p2 = _k < D[2], p3 = _k < D[3];       \
    unsigned n3 = p3 ? (p2 ? D[2] : _k) : D[3];  int m3 = p3 ? (p2 ? J[2] : _j) : J[3]; \
    unsigned n2 = p2 ? (p1 ? D[1] : _k) : D[2];  int m2 = p2 ? (p1 ? J[1] : _j) : J[2]; \
    unsigned n1 = p1 ? (p0 ? D[0] : _k) : D[1];  int m1 = p1 ? (p0 ? J[0] : _j) : J[1]; \
    unsigned n0 = p0 ? _k : D[0];                int m0 = p0 ? _j : J[0];      \
    D[0]=n0; D[1]=n1; D[2]=n2; D[3]=n3;                                        \
    J[0]=m0; J[1]=m1; J[2]=m2; J[3]=m3;                                        \
} while (0)

__global__ void knn_kernel(float2* __restrict__ out)
{
    // Scratch for the rare exact depth-16 fallback (32 KB).
    __shared__ unsigned sD[WPC][KNN][32];
    __shared__ int      sJ[WPC][KNN][32];

    const int b    = blockIdx.y;
    const int wid  = threadIdx.x >> 5;
    const int lane = threadIdx.x & 31;
    const int q    = blockIdx.x * WPC + wid;           // 0..2047 exactly

    const float4 q0 = T4g[b][0][q];
    const float4 q1 = T4g[b][1][q];
    const float4 q2 = T4g[b][2][q];
    const float4 q3 = T4g[b][3][q];

    unsigned D[KL];
    int      J[KL];
#pragma unroll
    for (int i = 0; i < KL; ++i) { D[i] = 0xFFFFFFFFu; J[i] = 0x7FFFFFFF; }

    // Pass: 2 candidates per iteration -> two independent FP chains in flight.
#pragma unroll 1
    for (int t = 0; t < NPTS / 32; t += 2) {
        const int ja = t * 32 + lane;
        const int jb = ja + 32;

        float4 x0 = T4g[b][0][ja], x1 = T4g[b][1][ja],
               x2 = T4g[b][2][ja], x3 = T4g[b][3][ja];
        float4 y0 = T4g[b][0][jb], y1 = T4g[b][1][jb],
               y2 = T4g[b][2][jb], y3 = T4g[b][3][jb];

        unsigned ka = dist_key(q0, q1, q2, q3, x0, x1, x2, x3);
        unsigned kb2 = dist_key(q0, q1, q2, q3, y0, y1, y2, y3);
        if (ja == q)  ka  = 0xFFFFFFFFu;
        if (jb == q)  kb2 = 0xFFFFFFFFu;

        INSERT4(ka, ja);
        INSERT4(kb2, jb);
    }

    // 16-round warp-min merge over unique 64-bit keys; count pops per lane.
    float2* outp = out + ((size_t)b * NPTS + q) * KNN;
    const float fb = (float)b;
    int cnt = 0;
    unsigned long long h = ((unsigned long long)D[0] << 32) | (unsigned)J[0];
#pragma unroll
    for (int r = 0; r < KNN; ++r) {
        unsigned long long v = h;
#pragma unroll
        for (int off = 16; off > 0; off >>= 1) {
            unsigned long long o = __shfl_xor_sync(0xFFFFFFFFu, v, off);
            v = (o < v) ? o : v;
        }
        if (lane == 0)
            outp[r] = make_float2(fb, (float)(int)(unsigned)(v & 0xFFFFFFFFull));
        if (h == v) {
            ++cnt;
#pragma unroll
            for (int i = 0; i < KL - 1; ++i) { D[i] = D[i + 1]; J[i] = J[i + 1]; }
            D[KL - 1] = 0xFFFFFFFFu; J[KL - 1] = 0x7FFFFFFF;
            h = ((unsigned long long)D[0] << 32) | (unsigned)J[0];
        }
    }

    // Guard: a fully-popped lane may have discarded a true top-16 member.
    if (__ballot_sync(0xFFFFFFFFu, cnt == KL) != 0) {
#pragma unroll 1
        for (int i = 0; i < KNN; ++i) { sD[wid][i][lane] = 0xFFFFFFFFu; sJ[wid][i][lane] = 0x7FFFFFFF; }
#pragma unroll 1
        for (int t = 0; t < NPTS / 32; ++t) {
            const int j = t * 32 + lane;
            float4 a0 = T4g[b][0][j], a1 = T4g[b][1][j],
                   a2 = T4g[b][2][j], a3 = T4g[b][3][j];
            unsigned kk = dist_key(q0, q1, q2, q3, a0, a1, a2, a3);
            if (j == q) continue;
            if (kk < sD[wid][KNN - 1][lane]) {
                int p = KNN - 1;
#pragma unroll 1
                while (p > 0 && kk < sD[wid][p - 1][lane]) {
                    sD[wid][p][lane] = sD[wid][p - 1][lane];
                    sJ[wid][p][lane] = sJ[wid][p - 1][lane];
                    --p;
                }
                sD[wid][p][lane] = kk; sJ[wid][p][lane] = j;
            }
        }
        int cur = 0;
        unsigned long long h2 = ((unsigned long long)sD[wid][0][lane] << 32)
                              | (unsigned)sJ[wid][0][lane];
#pragma unroll 1
        for (int r = 0; r < KNN; ++r) {
            unsigned long long v = h2;
#pragma unroll
            for (int off = 16; off > 0; off >>= 1) {
                unsigned long long o = __shfl_xor_sync(0xFFFFFFFFu, v, off);
                v = (o < v) ? o : v;
            }
            if (lane == 0)
                outp[r] = make_float2(fb, (float)(int)(unsigned)(v & 0xFFFFFFFFull));
            if (h2 == v) {
                ++cur;
                h2 = (cur < KNN)
                   ? (((unsigned long long)sD[wid][cur][lane] << 32) | (unsigned)sJ[wid][cur][lane])
                   : 0xFFFFFFFFFFFFFFFFull;
            }
        }
    }
}

extern "C" void kernel_launch(void* const* d_in, const int* in_sizes, int n_in,
                              void* d_out, int out_size)
{
    // points (2*2048*16) is the SMALLER input (features is 4x larger).
    const float* points;
    if (n_in >= 2) {
        points = (in_sizes[0] <= in_sizes[1]) ? (const float*)d_in[0]
                                              : (const float*)d_in[1];
    } else {
        points = (const float*)d_in[0];
    }

    transpose_kernel<<<(2 * 4 * NPTS + 255) / 256, 256>>>(points);

    dim3 grid(NPTS / WPC, 2);
    knn_kernel<<<grid, THREADS>>>((float2*)d_out);
}

// round 9
// speedup vs baseline: 2.2409x; 2.2409x over previous
#include <cuda_runtime.h>
#include <stdint.h>

// kNN: B=2, N=2048, D=16, K=16. Output (B,N,K,2) FLOAT32: [b, idx].
//
// transpose_kernel: AoS points -> SoA float4 scratch (coalesced loads).
// knn_kernel: TWO WARPS PER QUERY (each scans 1024 candidates, 32 steps),
// R6-proven per-lane sorted top-8 branchy insert + 16-round warp-min pop
// merge (64-bit keys dist_bits<<32|idx, exact jax.lax.top_k tie semantics).
// Round-r winner captured by lane r. Warp pair then combines its two sorted
// 16-lists via one 5-stage bitonic merge; even warp writes the output.
// Guard: lane popping all 8 -> exact depth-16 SMEM fallback for that half.

#define NPTS 2048
#define KNN  16
#define KL   8
#define WPC  8                     // 8 warps = 4 queries per CTA
#define THREADS (WPC * 32)
#define HALF_STEPS 32              // 1024 candidates / 32 lanes

__device__ float4 T4g[2][4][NPTS];   // 256 KB static scratch

__global__ void transpose_kernel(const float* __restrict__ points)
{
    int idx = blockIdx.x * blockDim.x + threadIdx.x;   // b*8192 + c*2048 + j
    if (idx >= 2 * 4 * NPTS) return;
    int j = idx & (NPTS - 1);
    int c = (idx >> 11) & 3;
    int b = idx >> 13;
    const float4* P4 = reinterpret_cast<const float4*>(points);
    T4g[b][c][j] = P4[(b * NPTS + j) * 4 + c];
}

__device__ __forceinline__ unsigned dist_key(
    float4 q0, float4 q1, float4 q2, float4 q3,
    float4 a0, float4 a1, float4 a2, float4 a3)
{
    float s = 0.0f, d;
    d = q0.x - a0.x; s = fmaf(d, d, s);
    d = q0.y - a0.y; s = fmaf(d, d, s);
    d = q0.z - a0.z; s = fmaf(d, d, s);
    d = q0.w - a0.w; s = fmaf(d, d, s);
    d = q1.x - a1.x; s = fmaf(d, d, s);
    d = q1.y - a1.y; s = fmaf(d, d, s);
    d = q1.z - a1.z; s = fmaf(d, d, s);
    d = q1.w - a1.w; s = fmaf(d, d, s);
    d = q2.x - a2.x; s = fmaf(d, d, s);
    d = q2.y - a2.y; s = fmaf(d, d, s);
    d = q2.z - a2.z; s = fmaf(d, d, s);
    d = q2.w - a2.w; s = fmaf(d, d, s);
    d = q3.x - a3.x; s = fmaf(d, d, s);
    d = q3.y - a3.y; s = fmaf(d, d, s);
    d = q3.z - a3.z; s = fmaf(d, d, s);
    d = q3.w - a3.w; s = fmaf(d, d, s);
    return __float_as_uint(__fsqrt_rn(s));   // compare post-sqrt (ref semantics)
}

__device__ __forceinline__ unsigned long long umin64(unsigned long long a,
                                                     unsigned long long b)
{ return (b < a) ? b : a; }
__device__ __forceinline__ unsigned long long umax64(unsigned long long a,
                                                     unsigned long long b)
{ return (a < b) ? b : a; }

__global__ void knn_kernel(float2* __restrict__ out)
{
    __shared__ unsigned sD[WPC][KNN][32];            // fallback scratch (rare)
    __shared__ int      sJ[WPC][KNN][32];
    __shared__ unsigned long long sX[WPC][16];       // pair exchange

    const int b    = blockIdx.y;
    const int wid  = threadIdx.x >> 5;
    const int lane = threadIdx.x & 31;
    const int pair = wid >> 1;
    const int half = wid & 1;
    const int q    = blockIdx.x * 4 + pair;          // 0..2047
    const int jbase = half * (NPTS / 2);             // this warp's candidate half

    const float4 q0 = T4g[b][0][q];
    const float4 q1 = T4g[b][1][q];
    const float4 q2 = T4g[b][2][q];
    const float4 q3 = T4g[b][3][q];

    // ---- R6-proven pass over 1024 candidates: per-lane sorted top-8 ----
    unsigned D[KL];
    int      J[KL];
#pragma unroll
    for (int i = 0; i < KL; ++i) { D[i] = 0xFFFFFFFFu; J[i] = 0x7FFFFFFF; }

#pragma unroll 2
    for (int t = 0; t < HALF_STEPS; ++t) {
        const int j = jbase + t * 32 + lane;
        float4 a0 = T4g[b][0][j];
        float4 a1 = T4g[b][1][j];
        float4 a2 = T4g[b][2][j];
        float4 a3 = T4g[b][3][j];
        unsigned kb = dist_key(q0, q1, q2, q3, a0, a1, a2, a3);
        if (j == q) kb = 0xFFFFFFFFu;                // exclude self

        if (kb < D[KL - 1]) {                        // stable strict-<
            D[KL - 1] = kb; J[KL - 1] = j;
#pragma unroll
            for (int i = KL - 1; i > 0; --i) {
                if (D[i] < D[i - 1]) {
                    unsigned td = D[i]; D[i] = D[i - 1]; D[i - 1] = td;
                    int      tj = J[i]; J[i] = J[i - 1]; J[i - 1] = tj;
                }
            }
        }
    }

    // ---- 16-round warp-min pop merge; lane r captures round-r winner ----
    unsigned long long keep = 0xFFFFFFFFFFFFFFFFull;
    int cnt = 0;
    unsigned long long h = ((unsigned long long)D[0] << 32) | (unsigned)J[0];
#pragma unroll
    for (int r = 0; r < KNN; ++r) {
        unsigned long long v = h;
#pragma unroll
        for (int off = 16; off > 0; off >>= 1)
            v = umin64(v, __shfl_xor_sync(0xFFFFFFFFu, v, off));
        if (lane == r) keep = v;
        if (h == v) {                                // real keys unique
            ++cnt;
#pragma unroll
            for (int i = 0; i < KL - 1; ++i) { D[i] = D[i + 1]; J[i] = J[i + 1]; }
            D[KL - 1] = 0xFFFFFFFFu; J[KL - 1] = 0x7FFFFFFF;
            h = ((unsigned long long)D[0] << 32) | (unsigned)J[0];
        }
    }

    // ---- Guard: fully-popped lane may have discarded a needed 9th entry ----
    if (__ballot_sync(0xFFFFFFFFu, cnt == KL) != 0) {
#pragma unroll 1
        for (int i = 0; i < KNN; ++i) { sD[wid][i][lane] = 0xFFFFFFFFu; sJ[wid][i][lane] = 0x7FFFFFFF; }
#pragma unroll 1
        for (int t = 0; t < HALF_STEPS; ++t) {
            const int j = jbase + t * 32 + lane;
            float4 a0 = T4g[b][0][j], a1 = T4g[b][1][j],
                   a2 = T4g[b][2][j], a3 = T4g[b][3][j];
            unsigned kk = dist_key(q0, q1, q2, q3, a0, a1, a2, a3);
            if (j == q) continue;
            if (kk < sD[wid][KNN - 1][lane]) {
                int p = KNN - 1;
#pragma unroll 1
                while (p > 0 && kk < sD[wid][p - 1][lane]) {
                    sD[wid][p][lane] = sD[wid][p - 1][lane];
                    sJ[wid][p][lane] = sJ[wid][p - 1][lane];
                    --p;
                }
                sD[wid][p][lane] = kk; sJ[wid][p][lane] = j;
            }
        }
        int cur = 0;
        unsigned long long h2 = ((unsigned long long)sD[wid][0][lane] << 32)
                              | (unsigned)sJ[wid][0][lane];
#pragma unroll 1
        for (int r = 0; r < KNN; ++r) {
            unsigned long long v = h2;
#pragma unroll
            for (int off = 16; off > 0; off >>= 1)
                v = umin64(v, __shfl_xor_sync(0xFFFFFFFFu, v, off));
            if (lane == r) keep = v;
            if (h2 == v) {
                ++cur;
                h2 = (cur < KNN)
                   ? (((unsigned long long)sD[wid][cur][lane] << 32) | (unsigned)sJ[wid][cur][lane])
                   : 0xFFFFFFFFFFFFFFFFull;
            }
        }
    }

    // ---- Exchange + cross-half bitonic merge (even warp of each pair) ----
    if (lane < 16) sX[wid][lane] = keep;
    __syncthreads();

    if (half == 0) {
        // lanes 0..15: own ascending list; lanes 16..31: partner reversed.
        unsigned long long X = (lane < 16) ? keep : sX[wid + 1][31 - lane];
        // Bitonic merge (asc): input is ascending++descending = bitonic.
#pragma unroll
        for (int off = 16; off > 0; off >>= 1) {
            unsigned long long o = __shfl_xor_sync(0xFFFFFFFFu, X, off);
            X = (lane & off) ? umax64(X, o) : umin64(X, o);
        }
        if (lane < 16) {
            float2* outp = out + ((size_t)b * NPTS + q) * KNN;
            outp[lane] = make_float2((float)b,
                                     (float)(int)(unsigned)(X & 0xFFFFFFFFull));
        }
    }
}

extern "C" void kernel_launch(void* const* d_in, const int* in_sizes, int n_in,
                              void* d_out, int out_size)
{
    // points (2*2048*16) is the SMALLER input (features is 4x larger).
    const float* points;
    if (n_in >= 2) {
        points = (in_sizes[0] <= in_sizes[1]) ? (const float*)d_in[0]
                                              : (const float*)d_in[1];
    } else {
        points = (const float*)d_in[0];
    }

    transpose_kernel<<<(2 * 4 * NPTS + 255) / 256, 256>>>(points);

    dim3 grid(NPTS / 4, 2);          // 4 queries per CTA (8 warps), 1024 CTAs
    knn_kernel<<<grid, THREADS>>>((float2*)d_out);
}